// round 6
// baseline (speedup 1.0000x reference)
#include <cuda_runtime.h>
#include <cuda_fp16.h>
#include <cstdint>
#include <cstddef>

// Problem dims (fixed by reference)
#define TDIM 1024
#define BDIM 32
#define DIN  256
#define HDIM 256
#define AADIM 21

// Scratch (device globals: allocation-guard safe)
// U layout PERMUTED: (T, B, dir, H, 4) — float4 per (t,b,dir,h)
__device__ float  g_U   [ (size_t)TDIM * BDIM * 8 * HDIM ];   // 256 MB fp32
__device__ __half g_H0h [ (size_t)TDIM * BDIM * 2 * HDIM ];   // 32 MB fp16 (T,B,2H)
__device__ __half g_H1h [ (size_t)TDIM * BDIM * 2 * HDIM ];   // 32 MB
__device__ float  g_Y   [ (size_t)TDIM * BDIM * HDIM ];       // 32 MB (T*B, H)
__device__ __half g_Xh  [ (size_t)BDIM * TDIM * DIN ];        // x in fp16 (B,T,DIN)
__device__ __half g_WPT0[ 2048 * DIN ];                       // w_l0 perm+T fp16 [2048][256]
__device__ __half g_WPT1[ 2048 * 2 * HDIM ];                  // w_l1 perm+T fp16 [2048][512]
__device__ __half g_FC1h[ HDIM * 2 * HDIM ];                  // fc1_w fp16 [256][512]

__device__ __forceinline__ void cp16(uint32_t dst, const void* src) {
    asm volatile("cp.async.cg.shared.global [%0], [%1], 16;" :: "r"(dst), "l"(src));
}
__device__ __forceinline__ uint32_t su32(const void* p) {
    return (uint32_t)__cvta_generic_to_shared(p);
}

// ===========================================================================
// fp16 tensor-core GEMM: C[M,N](fp32) = A[M,K](fp16) @ B^T (B fp16 [N][K])
// Block 128x128, 256 threads = 8 warps (2x4), warp tile 64x32.
// mma.m16n8k16.f32.f16.f16.f32, BK=32 halves, 3-stage cp.async pipeline.
// XMODE: A row m -> x[b][t] with t=m/32, b=m%32 (x is (B,T,K)).
// ===========================================================================
#define BKH   32                       // halves per K tile
#define LDKH  40                       // padded halves per smem row (80 B)
#define LDKW  20                       // 32-bit words per smem row
#define TILEB (128 * LDKH * 2)         // 10240 bytes per operand tile
#define STGB  (2 * TILEB)              // 20480 bytes per stage
#define GSMEM (3 * STGB)               // 61440 bytes

template<bool XMODE, bool BIAS>
__global__ __launch_bounds__(256)
void h_gemm(const __half* __restrict__ A, const __half* __restrict__ Bw,
            float* __restrict__ C, int M, int N, int K,
            const float* __restrict__ bias)
{
    extern __shared__ char smem[];
    const uint32_t smem_u = su32(smem);

    const int tid  = threadIdx.x;
    const int lane = tid & 31;
    const int wid  = tid >> 5;
    const int bm = blockIdx.y * 128;
    const int bn = blockIdx.x * 128;
    const int wm = (wid & 1) * 64;
    const int wn = (wid >> 1) * 32;
    const int g2 = lane >> 2;      // 0..7
    const int g4 = lane & 3;       // 0..3

    float acc[4][4][4];
    #pragma unroll
    for (int mi = 0; mi < 4; mi++)
        #pragma unroll
        for (int ni = 0; ni < 4; ni++)
            #pragma unroll
            for (int r = 0; r < 4; r++)
                acc[mi][ni][r] = 0.f;

    const int T_t = K / BKH;

    // Each thread moves 2 x 16B for A and 2 x 16B for B per tile.
    // id = tid + p*256 -> row = id>>2 (0..127), chunk c = id&3 (16B each).
    #define ISSUE(tile, buf)                                                  \
    {                                                                         \
        const int k0_ = (tile) * BKH;                                         \
        const uint32_t as_ = smem_u + (buf) * STGB;                           \
        const uint32_t bs_ = as_ + TILEB;                                     \
        _Pragma("unroll")                                                     \
        for (int p = 0; p < 2; p++) {                                         \
            int id  = tid + p * 256;                                          \
            int row = id >> 2;                                                \
            int c   = id & 3;                                                 \
            size_t aoff;                                                      \
            int gm = bm + row;                                                \
            if (XMODE) {                                                      \
                int t_ = gm >> 5, bb = gm & 31;                               \
                aoff = ((size_t)bb * TDIM + t_) * (size_t)K + k0_ + c * 8;    \
            } else {                                                          \
                aoff = (size_t)gm * K + k0_ + c * 8;                          \
            }                                                                 \
            cp16(as_ + row * (LDKH * 2) + c * 16, A + aoff);                  \
            cp16(bs_ + row * (LDKH * 2) + c * 16,                             \
                 Bw + (size_t)(bn + row) * K + k0_ + c * 8);                  \
        }                                                                     \
        asm volatile("cp.async.commit_group;");                               \
    }

    ISSUE(0, 0);
    ISSUE(1, 1);

    for (int t = 0; t < T_t; t++) {
        if (t + 1 < T_t) asm volatile("cp.async.wait_group 1;");
        else             asm volatile("cp.async.wait_group 0;");
        __syncthreads();

        if (t + 2 < T_t) ISSUE(t + 2, (t + 2) % 3);

        const uint32_t* sa = (const uint32_t*)(smem + (t % 3) * STGB);
        const uint32_t* sb = (const uint32_t*)(smem + (t % 3) * STGB + TILEB);

        #pragma unroll
        for (int kk = 0; kk < 2; kk++) {
            const int kw = kk * 8 + g4;      // word index within row
            uint32_t af[4][4], bf[4][2];
            #pragma unroll
            for (int mt = 0; mt < 4; mt++) {
                int r0 = wm + mt * 16 + g2;
                af[mt][0] = sa[r0 * LDKW + kw];
                af[mt][1] = sa[(r0 + 8) * LDKW + kw];
                af[mt][2] = sa[r0 * LDKW + kw + 4];
                af[mt][3] = sa[(r0 + 8) * LDKW + kw + 4];
            }
            #pragma unroll
            for (int nt = 0; nt < 4; nt++) {
                int n0 = wn + nt * 8 + g2;
                bf[nt][0] = sb[n0 * LDKW + kw];
                bf[nt][1] = sb[n0 * LDKW + kw + 4];
            }
            #pragma unroll
            for (int mt = 0; mt < 4; mt++)
                #pragma unroll
                for (int nt = 0; nt < 4; nt++) {
                    asm volatile(
                        "mma.sync.aligned.m16n8k16.row.col.f32.f16.f16.f32 "
                        "{%0,%1,%2,%3}, {%4,%5,%6,%7}, {%8,%9}, {%0,%1,%2,%3};"
                        : "+f"(acc[mt][nt][0]), "+f"(acc[mt][nt][1]),
                          "+f"(acc[mt][nt][2]), "+f"(acc[mt][nt][3])
                        : "r"(af[mt][0]), "r"(af[mt][1]),
                          "r"(af[mt][2]), "r"(af[mt][3]),
                          "r"(bf[nt][0]), "r"(bf[nt][1]));
                }
        }
    }
    #undef ISSUE

    // store C (+bias): c0,c1 -> (row, col+{0,1}); c2,c3 -> (row+8, ...)
    #pragma unroll
    for (int mt = 0; mt < 4; mt++) {
        int row0 = bm + wm + mt * 16 + g2;
        #pragma unroll
        for (int nt = 0; nt < 4; nt++) {
            int col = bn + wn + nt * 8 + 2 * g4;
            float bx = 0.f, by = 0.f;
            if (BIAS) { bx = bias[col]; by = bias[col + 1]; }
            float2 v0 = make_float2(acc[mt][nt][0] + bx, acc[mt][nt][1] + by);
            float2 v1 = make_float2(acc[mt][nt][2] + bx, acc[mt][nt][3] + by);
            *(float2*)(C + (size_t)row0 * N + col)       = v0;
            *(float2*)(C + (size_t)(row0 + 8) * N + col) = v1;
        }
    }
}

// ---------------------------------------------------------------------------
// Prep: fp32 -> fp16 conversions
// ---------------------------------------------------------------------------
__global__ void conv_h(const float* __restrict__ in, __half* __restrict__ out,
                       int n)
{
    int i = blockIdx.x * blockDim.x + threadIdx.x;
    if (i < n) out[i] = __float2half(in[i]);
}

// Permute + transpose weights to fp16: wpt[p][k] = w[k][n(p)].
// p = dir*1024 + h*4 + kk  ->  n = dir*1024 + kk*256 + h.
__global__ void permute_wT_h(const float* __restrict__ w, __half* __restrict__ wpt,
                             int K)
{
    int idx = blockIdx.x * blockDim.x + threadIdx.x;   // p-major, k fastest
    if (idx >= 2048 * K) return;
    int p = idx / K;
    int k = idx % K;
    int dir = p >> 10;
    int h   = (p & 1023) >> 2;
    int kk  = p & 3;
    int n   = dir * 1024 + kk * 256 + h;
    wpt[idx] = __float2half(w[(size_t)k * 2048 + n]);
}

// ---------------------------------------------------------------------------
// SRU scan, float4 U layout (T,B,dir,H,4), depth-16 ring buffer; fp16 output.
// ---------------------------------------------------------------------------
#define SCAN_D 16

__global__ __launch_bounds__(64)
void sru_scan_kernel(const float4* __restrict__ U4, const float* __restrict__ wc,
                     const float* __restrict__ bvec, __half* __restrict__ Hout)
{
    const int q   = HDIM / 64;                       // 4
    const int bi  = blockIdx.x;
    const int dir = bi / (BDIM * q);
    const int b   = (bi / q) % BDIM;
    const int h   = (bi % q) * 64 + threadIdx.x;

    const float vf = wc[(dir * 2 + 0) * HDIM + h];
    const float vr = wc[(dir * 2 + 1) * HDIM + h];
    const float bf = bvec[(dir * 2 + 0) * HDIM + h];
    const float br = bvec[(dir * 2 + 1) * HDIM + h];

    const int t0 = dir ? (TDIM - 1) : 0;
    const long dt = dir ? -1 : 1;

    const float4* up = U4 + (((size_t)t0 * BDIM + b) * 2 + dir) * HDIM + h;
    __half* hp = Hout + ((size_t)t0 * BDIM + b) * (2 * HDIM)
                      + (size_t)dir * HDIM + h;
    const long ustep = dt * (long)BDIM * 2 * HDIM;    // float4 units
    const long hstep = dt * (long)BDIM * 2 * HDIM;    // half units

    float4 ring[SCAN_D];
    const float4* lp = up;
    #pragma unroll
    for (int d = 0; d < SCAN_D; d++) { ring[d] = *lp; lp += ustep; }

    float c = 0.f;
    for (int s0 = 0; s0 < TDIM; s0 += SCAN_D) {
        #pragma unroll
        for (int d = 0; d < SCAN_D; d++) {
            float4 u = ring[d];
            if (s0 + d + SCAN_D < TDIM) { ring[d] = *lp; lp += ustep; }
            float f  = 1.f / (1.f + __expf(-(u.y + vf * c + bf)));
            float c2 = f * c + (1.f - f) * u.x;
            float r  = 1.f / (1.f + __expf(-(u.z + vr * c + br)));
            float hv = r * c2 + (1.f - r) * u.w;
            c = c2;
            *hp = __float2half(hv);
            hp += hstep;
        }
    }
}

// ---------------------------------------------------------------------------
// logits = log_softmax(Y @ lp_w^T + lp_b). 4 rows per warp, 32 rows/block.
// ---------------------------------------------------------------------------
__global__ __launch_bounds__(256)
void logits_kernel(const float* __restrict__ Y, const float* __restrict__ lp_w,
                   const float* __restrict__ lp_b, float* __restrict__ out)
{
    __shared__ float ws[AADIM * HDIM];
    __shared__ float bs[32];
    const int tid = threadIdx.x;
    for (int i = tid; i < AADIM * HDIM; i += blockDim.x) ws[i] = lp_w[i];
    if (tid < AADIM) bs[tid] = lp_b[tid];
    __syncthreads();

    const int warp = tid >> 5;
    const int lane = tid & 31;

    #pragma unroll
    for (int rr = 0; rr < 4; rr++) {
        const int row = blockIdx.x * 32 + warp * 4 + rr;   // row = t*B + b
        const int t = row / BDIM;
        const int b = row % BDIM;

        const float* y = Y + (size_t)row * HDIM;
        float yv[8];
        #pragma unroll
        for (int i = 0; i < 8; i++) yv[i] = y[lane + 32 * i];

        float lg[AADIM];
        #pragma unroll
        for (int a = 0; a < AADIM; a++) {
            float s = 0.f;
            #pragma unroll
            for (int i = 0; i < 8; i++) s += yv[i] * ws[a * HDIM + lane + 32 * i];
            #pragma unroll
            for (int off = 16; off > 0; off >>= 1)
                s += __shfl_xor_sync(0xFFFFFFFFu, s, off);
            lg[a] = s + bs[a];
        }

        float mx = lg[0];
        #pragma unroll
        for (int a = 1; a < AADIM; a++) mx = fmaxf(mx, lg[a]);
        float se = 0.f;
        #pragma unroll
        for (int a = 0; a < AADIM; a++) se += __expf(lg[a] - mx);
        float lse = mx + __logf(se);

        float myv = 0.f;
        #pragma unroll
        for (int a = 0; a < AADIM; a++) if (lane == a) myv = lg[a] - lse;
        if (lane < AADIM)
            out[((size_t)b * TDIM + t) * AADIM + lane] = myv;
    }
}

// ---------------------------------------------------------------------------
extern "C" void kernel_launch(void* const* d_in, const int* in_sizes, int n_in,
                              void* d_out, int out_size)
{
    const float* x     = (const float*)d_in[0];
    // d_in[1] = hidden (unused)
    const float* w_l0  = (const float*)d_in[2];
    const float* wc_l0 = (const float*)d_in[3];
    const float* b_l0  = (const float*)d_in[4];
    const float* w_l1  = (const float*)d_in[5];
    const float* wc_l1 = (const float*)d_in[6];
    const float* b_l1  = (const float*)d_in[7];
    const float* fc1_w = (const float*)d_in[8];
    const float* fc1_b = (const float*)d_in[9];
    const float* lp_w  = (const float*)d_in[10];
    const float* lp_b  = (const float*)d_in[11];
    float* out = (float*)d_out;

    float *pU, *pY;
    __half *pH0h, *pH1h, *pXh, *pWPT0, *pWPT1, *pFC1h;
    cudaGetSymbolAddress((void**)&pU,    g_U);
    cudaGetSymbolAddress((void**)&pY,    g_Y);
    cudaGetSymbolAddress((void**)&pH0h,  g_H0h);
    cudaGetSymbolAddress((void**)&pH1h,  g_H1h);
    cudaGetSymbolAddress((void**)&pXh,   g_Xh);
    cudaGetSymbolAddress((void**)&pWPT0, g_WPT0);
    cudaGetSymbolAddress((void**)&pWPT1, g_WPT1);
    cudaGetSymbolAddress((void**)&pFC1h, g_FC1h);

    cudaFuncSetAttribute(h_gemm<true,  false>,
        cudaFuncAttributeMaxDynamicSharedMemorySize, GSMEM);
    cudaFuncSetAttribute(h_gemm<false, false>,
        cudaFuncAttributeMaxDynamicSharedMemorySize, GSMEM);
    cudaFuncSetAttribute(h_gemm<false, true>,
        cudaFuncAttributeMaxDynamicSharedMemorySize, GSMEM);

    const int M = TDIM * BDIM;      // 32768

    // prep conversions
    conv_h<<<(BDIM * TDIM * DIN + 255) / 256, 256>>>(x, pXh, BDIM * TDIM * DIN);
    permute_wT_h<<<(2048 * DIN + 255) / 256, 256>>>(w_l0, pWPT0, DIN);
    permute_wT_h<<<(2048 * 2 * HDIM + 255) / 256, 256>>>(w_l1, pWPT1, 2 * HDIM);
    conv_h<<<(HDIM * 2 * HDIM + 255) / 256, 256>>>(fc1_w, pFC1h, HDIM * 2 * HDIM);

    // GEMM1: U0 = x @ WPT0^T  [32768 x 2048 x 256]
    {
        dim3 grid(2048 / 128, M / 128);
        h_gemm<true, false><<<grid, 256, GSMEM>>>(pXh, pWPT0, pU, M, 2048, DIN, nullptr);
    }
    sru_scan_kernel<<<2 * BDIM * (HDIM / 64), 64>>>((const float4*)pU, wc_l0, b_l0, pH0h);

    // GEMM2: U1 = H0 @ WPT1^T  [32768 x 2048 x 512]
    {
        dim3 grid(2048 / 128, M / 128);
        h_gemm<false, false><<<grid, 256, GSMEM>>>(pH0h, pWPT1, pU, M, 2048, 2 * HDIM, nullptr);
    }
    sru_scan_kernel<<<2 * BDIM * (HDIM / 64), 64>>>((const float4*)pU, wc_l1, b_l1, pH1h);

    // GEMM3: Y = H1 @ fc1_w^T + fc1_b  [32768 x 256 x 512]  (fc1_w is [N][K])
    {
        dim3 grid(HDIM / 128, M / 128);
        h_gemm<false, true><<<grid, 256, GSMEM>>>(pH1h, pFC1h, pY, M, HDIM, 2 * HDIM, fc1_b);
    }

    // logits + log_softmax
    logits_kernel<<<M / 32, 256>>>(pY, lp_w, lp_b, out);
}

// round 7
// speedup vs baseline: 1.6732x; 1.6732x over previous
#include <cuda_runtime.h>
#include <cuda_fp16.h>
#include <cstdint>
#include <cstddef>

// Problem dims (fixed by reference)
#define TDIM 1024
#define BDIM 32
#define DIN  256
#define HDIM 256
#define AADIM 21

// Scratch (device globals: allocation-guard safe)
// U layout PERMUTED, fp16: (T, B, dir, H, 4) — uint2 (4 halves) per (t,b,dir,h)
__device__ __half g_Uh  [ (size_t)TDIM * BDIM * 8 * HDIM ];   // 128 MB fp16
__device__ __half g_H0h [ (size_t)TDIM * BDIM * 2 * HDIM ];   // 32 MB fp16 (T,B,2H)
__device__ __half g_H1h [ (size_t)TDIM * BDIM * 2 * HDIM ];   // 32 MB
__device__ float  g_Y   [ (size_t)TDIM * BDIM * HDIM ];       // 32 MB (T*B, H)
__device__ __half g_Xh  [ (size_t)BDIM * TDIM * DIN ];        // x fp16 (B,T,DIN)
__device__ __half g_WPT0[ 2048 * DIN ];                       // w_l0 perm+T fp16 [2048][256]
__device__ __half g_WPT1[ 2048 * 2 * HDIM ];                  // w_l1 perm+T fp16 [2048][512]
__device__ __half g_FC1h[ HDIM * 2 * HDIM ];                  // fc1_w fp16 [256][512]

__device__ __forceinline__ void cp16(uint32_t dst, const void* src) {
    asm volatile("cp.async.cg.shared.global [%0], [%1], 16;" :: "r"(dst), "l"(src));
}
__device__ __forceinline__ uint32_t su32(const void* p) {
    return (uint32_t)__cvta_generic_to_shared(p);
}
__device__ __forceinline__ float fast_rcp(float x) {
    float r;
    asm("rcp.approx.f32 %0, %1;" : "=f"(r) : "f"(x));
    return r;
}
__device__ __forceinline__ float fast_ex2(float x) {
    float r;
    asm("ex2.approx.f32 %0, %1;" : "=f"(r) : "f"(x));
    return r;
}

// ===========================================================================
// fp16 tensor-core GEMM: C[M,N] = A[M,K](fp16) @ B^T (B fp16 [N][K])
// Block 128x128, 256 threads = 8 warps (2x4), warp tile 64x32.
// mma.m16n8k16.f32.f16.f16.f32, BK=32 halves, 3-stage cp.async pipeline.
// OUTH: C is fp16, stored via smem-staged fully-coalesced 32B/thread STG.
// XMODE: A row m -> x[b][t] with t=m/32, b=m%32 (x is (B,T,K)).
// ===========================================================================
#define BKH   32                       // halves per K tile
#define LDKH  40                       // padded halves per smem row (80 B)
#define LDKW  20                       // 32-bit words per smem row
#define TILEB (128 * LDKH * 2)         // 10240 bytes per operand tile
#define STGB  (2 * TILEB)              // 20480 bytes per stage
#define GSMEM (3 * STGB)               // 61440 bytes
#define EPILD 136                      // epilogue stage row stride (halves)

template<bool XMODE, bool OUTH, bool BIAS>
__global__ __launch_bounds__(256)
void h_gemm(const __half* __restrict__ A, const __half* __restrict__ Bw,
            void* __restrict__ Cv, int M, int N, int K,
            const float* __restrict__ bias)
{
    extern __shared__ char smem[];
    const uint32_t smem_u = su32(smem);

    const int tid  = threadIdx.x;
    const int lane = tid & 31;
    const int wid  = tid >> 5;
    const int bm = blockIdx.y * 128;
    const int bn = blockIdx.x * 128;
    const int wm = (wid & 1) * 64;
    const int wn = (wid >> 1) * 32;
    const int g2 = lane >> 2;      // 0..7
    const int g4 = lane & 3;       // 0..3

    float acc[4][4][4];
    #pragma unroll
    for (int mi = 0; mi < 4; mi++)
        #pragma unroll
        for (int ni = 0; ni < 4; ni++)
            #pragma unroll
            for (int r = 0; r < 4; r++)
                acc[mi][ni][r] = 0.f;

    const int T_t = K / BKH;

    #define ISSUE(tile, buf)                                                  \
    {                                                                         \
        const int k0_ = (tile) * BKH;                                         \
        const uint32_t as_ = smem_u + (buf) * STGB;                           \
        const uint32_t bs_ = as_ + TILEB;                                     \
        _Pragma("unroll")                                                     \
        for (int p = 0; p < 2; p++) {                                         \
            int id  = tid + p * 256;                                          \
            int row = id >> 2;                                                \
            int c   = id & 3;                                                 \
            size_t aoff;                                                      \
            int gm = bm + row;                                                \
            if (XMODE) {                                                      \
                int t_ = gm >> 5, bb = gm & 31;                               \
                aoff = ((size_t)bb * TDIM + t_) * (size_t)K + k0_ + c * 8;    \
            } else {                                                          \
                aoff = (size_t)gm * K + k0_ + c * 8;                          \
            }                                                                 \
            cp16(as_ + row * (LDKH * 2) + c * 16, A + aoff);                  \
            cp16(bs_ + row * (LDKH * 2) + c * 16,                             \
                 Bw + (size_t)(bn + row) * K + k0_ + c * 8);                  \
        }                                                                     \
        asm volatile("cp.async.commit_group;");                               \
    }

    ISSUE(0, 0);
    ISSUE(1, 1);

    for (int t = 0; t < T_t; t++) {
        if (t + 1 < T_t) asm volatile("cp.async.wait_group 1;");
        else             asm volatile("cp.async.wait_group 0;");
        __syncthreads();

        if (t + 2 < T_t) ISSUE(t + 2, (t + 2) % 3);

        const uint32_t* sa = (const uint32_t*)(smem + (t % 3) * STGB);
        const uint32_t* sb = (const uint32_t*)(smem + (t % 3) * STGB + TILEB);

        #pragma unroll
        for (int kk = 0; kk < 2; kk++) {
            const int kw = kk * 8 + g4;      // word index within row
            uint32_t af[4][4], bf[4][2];
            #pragma unroll
            for (int mt = 0; mt < 4; mt++) {
                int r0 = wm + mt * 16 + g2;
                af[mt][0] = sa[r0 * LDKW + kw];
                af[mt][1] = sa[(r0 + 8) * LDKW + kw];
                af[mt][2] = sa[r0 * LDKW + kw + 4];
                af[mt][3] = sa[(r0 + 8) * LDKW + kw + 4];
            }
            #pragma unroll
            for (int nt = 0; nt < 4; nt++) {
                int n0 = wn + nt * 8 + g2;
                bf[nt][0] = sb[n0 * LDKW + kw];
                bf[nt][1] = sb[n0 * LDKW + kw + 4];
            }
            #pragma unroll
            for (int mt = 0; mt < 4; mt++)
                #pragma unroll
                for (int nt = 0; nt < 4; nt++) {
                    asm volatile(
                        "mma.sync.aligned.m16n8k16.row.col.f32.f16.f16.f32 "
                        "{%0,%1,%2,%3}, {%4,%5,%6,%7}, {%8,%9}, {%0,%1,%2,%3};"
                        : "+f"(acc[mt][nt][0]), "+f"(acc[mt][nt][1]),
                          "+f"(acc[mt][nt][2]), "+f"(acc[mt][nt][3])
                        : "r"(af[mt][0]), "r"(af[mt][1]),
                          "r"(af[mt][2]), "r"(af[mt][3]),
                          "r"(bf[nt][0]), "r"(bf[nt][1]));
                }
        }
    }
    #undef ISSUE

    if (OUTH) {
        // fp16 output: stage 32x128 chunks in smem, store coalesced
        __half* Ch = (__half*)Cv;
        __half* st = (__half*)smem;
        #pragma unroll
        for (int mt = 0; mt < 4; mt++) {
            __syncthreads();
            const int srow = (wid & 1) * 16 + g2;
            #pragma unroll
            for (int nt = 0; nt < 4; nt++) {
                const int scol = wn + nt * 8 + 2 * g4;
                __half2 v01 = __floats2half2_rn(acc[mt][nt][0], acc[mt][nt][1]);
                __half2 v23 = __floats2half2_rn(acc[mt][nt][2], acc[mt][nt][3]);
                *(__half2*)&st[srow * EPILD + scol]       = v01;
                *(__half2*)&st[(srow + 8) * EPILD + scol] = v23;
            }
            __syncthreads();
            const int s   = tid >> 3;              // 0..31
            const int c16 = (tid & 7) * 16;        // 0..112
            const int crow = bm + (s >> 4) * 64 + mt * 16 + (s & 15);
            uint4 v0 = *(uint4*)&st[s * EPILD + c16];
            uint4 v1 = *(uint4*)&st[s * EPILD + c16 + 8];
            *(uint4*)(Ch + (size_t)crow * N + bn + c16)     = v0;
            *(uint4*)(Ch + (size_t)crow * N + bn + c16 + 8) = v1;
        }
    } else {
        float* C = (float*)Cv;
        #pragma unroll
        for (int mt = 0; mt < 4; mt++) {
            int row0 = bm + wm + mt * 16 + g2;
            #pragma unroll
            for (int nt = 0; nt < 4; nt++) {
                int col = bn + wn + nt * 8 + 2 * g4;
                float bx = 0.f, by = 0.f;
                if (BIAS) { bx = bias[col]; by = bias[col + 1]; }
                float2 v0 = make_float2(acc[mt][nt][0] + bx, acc[mt][nt][1] + by);
                float2 v1 = make_float2(acc[mt][nt][2] + bx, acc[mt][nt][3] + by);
                *(float2*)(C + (size_t)row0 * N + col)       = v0;
                *(float2*)(C + (size_t)(row0 + 8) * N + col) = v1;
            }
        }
    }
}

// ---------------------------------------------------------------------------
// Prep: fp32 -> fp16 conversions
// ---------------------------------------------------------------------------
__global__ void conv_h(const float* __restrict__ in, __half* __restrict__ out,
                       int n)
{
    int i = blockIdx.x * blockDim.x + threadIdx.x;
    if (i < n) out[i] = __float2half(in[i]);
}

// Permute + transpose weights to fp16: wpt[p][k] = w[k][n(p)].
__global__ void permute_wT_h(const float* __restrict__ w, __half* __restrict__ wpt,
                             int K)
{
    int idx = blockIdx.x * blockDim.x + threadIdx.x;   // p-major, k fastest
    if (idx >= 2048 * K) return;
    int p = idx / K;
    int k = idx % K;
    int dir = p >> 10;
    int h   = (p & 1023) >> 2;
    int kk  = p & 3;
    int n   = dir * 1024 + kk * 256 + h;
    wpt[idx] = __float2half(w[(size_t)k * 2048 + n]);
}

// ---------------------------------------------------------------------------
// SRU scan, fp16 U layout (T,B,dir,H,4) as uint2, depth-16 ring buffer.
// Critical chain: FFMA -> EX2 -> FADD -> RCP -> FFMA (~44cyc/step).
// ---------------------------------------------------------------------------
#define SCAN_D 16
#define LOG2E 1.4426950408889634f

__global__ __launch_bounds__(64)
void sru_scan_kernel(const uint2* __restrict__ U2, const float* __restrict__ wc,
                     const float* __restrict__ bvec, __half* __restrict__ Hout)
{
    const int q   = HDIM / 64;                       // 4
    const int bi  = blockIdx.x;
    const int dir = bi / (BDIM * q);
    const int b   = (bi / q) % BDIM;
    const int h   = (bi % q) * 64 + threadIdx.x;

    // fold -log2(e) into gate weights: exp(-(z)) = exp2(-z*log2e)
    const float nvf = -wc[(dir * 2 + 0) * HDIM + h] * LOG2E;
    const float nvr = -wc[(dir * 2 + 1) * HDIM + h] * LOG2E;
    const float nbf = -bvec[(dir * 2 + 0) * HDIM + h] * LOG2E;
    const float nbr = -bvec[(dir * 2 + 1) * HDIM + h] * LOG2E;

    const int t0 = dir ? (TDIM - 1) : 0;
    const long dt = dir ? -1 : 1;

    const uint2* up = U2 + (((size_t)t0 * BDIM + b) * 2 + dir) * HDIM + h;
    __half* hp = Hout + ((size_t)t0 * BDIM + b) * (2 * HDIM)
                      + (size_t)dir * HDIM + h;
    const long ustep = dt * (long)BDIM * 2 * HDIM;    // uint2 units
    const long hstep = dt * (long)BDIM * 2 * HDIM;    // half units

    uint2 ring[SCAN_D];
    const uint2* lp = up;
    #pragma unroll
    for (int d = 0; d < SCAN_D; d++) { ring[d] = *lp; lp += ustep; }

    float c = 0.f;
    for (int s0 = 0; s0 < TDIM; s0 += SCAN_D) {
        #pragma unroll
        for (int d = 0; d < SCAN_D; d++) {
            uint2 uw = ring[d];
            if (s0 + d + SCAN_D < TDIM) { ring[d] = *lp; lp += ustep; }
            float2 u01 = __half22float2(*(__half2*)&uw.x);   // (cand, forget)
            float2 u23 = __half22float2(*(__half2*)&uw.y);   // (reset, highway)
            // off-chain precompute
            float zf = fmaf(u01.y, -LOG2E, nbf);             // -(u1+bf)*log2e
            float zr = fmaf(u23.x, -LOG2E, nbr);
            float cmu0 = c - u01.x;
            // chain: FFMA -> EX2 -> FADD -> RCP -> FFMA
            float ef = fast_ex2(fmaf(nvf, c, zf));
            float f  = fast_rcp(1.f + ef);
            float c2 = fmaf(f, cmu0, u01.x);
            // r-gate off the next-step chain (uses old c)
            float er = fast_ex2(fmaf(nvr, c, zr));
            float r  = fast_rcp(1.f + er);
            float hv = fmaf(r, c2 - u23.y, u23.y);
            c = c2;
            *hp = __float2half(hv);
            hp += hstep;
        }
    }
}

// ---------------------------------------------------------------------------
// logits = log_softmax(Y @ lp_w^T + lp_b). 4 rows per warp, 32 rows/block.
// ---------------------------------------------------------------------------
__global__ __launch_bounds__(256)
void logits_kernel(const float* __restrict__ Y, const float* __restrict__ lp_w,
                   const float* __restrict__ lp_b, float* __restrict__ out)
{
    __shared__ float ws[AADIM * HDIM];
    __shared__ float bs[32];
    const int tid = threadIdx.x;
    for (int i = tid; i < AADIM * HDIM; i += blockDim.x) ws[i] = lp_w[i];
    if (tid < AADIM) bs[tid] = lp_b[tid];
    __syncthreads();

    const int warp = tid >> 5;
    const int lane = tid & 31;

    #pragma unroll
    for (int rr = 0; rr < 4; rr++) {
        const int row = blockIdx.x * 32 + warp * 4 + rr;   // row = t*B + b
        const int t = row / BDIM;
        const int b = row % BDIM;

        const float* y = Y + (size_t)row * HDIM;
        float yv[8];
        #pragma unroll
        for (int i = 0; i < 8; i++) yv[i] = y[lane + 32 * i];

        float lg[AADIM];
        #pragma unroll
        for (int a = 0; a < AADIM; a++) {
            float s = 0.f;
            #pragma unroll
            for (int i = 0; i < 8; i++) s += yv[i] * ws[a * HDIM + lane + 32 * i];
            #pragma unroll
            for (int off = 16; off > 0; off >>= 1)
                s += __shfl_xor_sync(0xFFFFFFFFu, s, off);
            lg[a] = s + bs[a];
        }

        float mx = lg[0];
        #pragma unroll
        for (int a = 1; a < AADIM; a++) mx = fmaxf(mx, lg[a]);
        float se = 0.f;
        #pragma unroll
        for (int a = 0; a < AADIM; a++) se += __expf(lg[a] - mx);
        float lse = mx + __logf(se);

        float myv = 0.f;
        #pragma unroll
        for (int a = 0; a < AADIM; a++) if (lane == a) myv = lg[a] - lse;
        if (lane < AADIM)
            out[((size_t)b * TDIM + t) * AADIM + lane] = myv;
    }
}

// ---------------------------------------------------------------------------
extern "C" void kernel_launch(void* const* d_in, const int* in_sizes, int n_in,
                              void* d_out, int out_size)
{
    const float* x     = (const float*)d_in[0];
    // d_in[1] = hidden (unused)
    const float* w_l0  = (const float*)d_in[2];
    const float* wc_l0 = (const float*)d_in[3];
    const float* b_l0  = (const float*)d_in[4];
    const float* w_l1  = (const float*)d_in[5];
    const float* wc_l1 = (const float*)d_in[6];
    const float* b_l1  = (const float*)d_in[7];
    const float* fc1_w = (const float*)d_in[8];
    const float* fc1_b = (const float*)d_in[9];
    const float* lp_w  = (const float*)d_in[10];
    const float* lp_b  = (const float*)d_in[11];
    float* out = (float*)d_out;

    float *pY;
    __half *pUh, *pH0h, *pH1h, *pXh, *pWPT0, *pWPT1, *pFC1h;
    cudaGetSymbolAddress((void**)&pUh,   g_Uh);
    cudaGetSymbolAddress((void**)&pY,    g_Y);
    cudaGetSymbolAddress((void**)&pH0h,  g_H0h);
    cudaGetSymbolAddress((void**)&pH1h,  g_H1h);
    cudaGetSymbolAddress((void**)&pXh,   g_Xh);
    cudaGetSymbolAddress((void**)&pWPT0, g_WPT0);
    cudaGetSymbolAddress((void**)&pWPT1, g_WPT1);
    cudaGetSymbolAddress((void**)&pFC1h, g_FC1h);

    cudaFuncSetAttribute(h_gemm<true,  true,  false>,
        cudaFuncAttributeMaxDynamicSharedMemorySize, GSMEM);
    cudaFuncSetAttribute(h_gemm<false, true,  false>,
        cudaFuncAttributeMaxDynamicSharedMemorySize, GSMEM);
    cudaFuncSetAttribute(h_gemm<false, false, true>,
        cudaFuncAttributeMaxDynamicSharedMemorySize, GSMEM);

    const int M = TDIM * BDIM;      // 32768

    // prep conversions
    conv_h<<<(BDIM * TDIM * DIN + 255) / 256, 256>>>(x, pXh, BDIM * TDIM * DIN);
    permute_wT_h<<<(2048 * DIN + 255) / 256, 256>>>(w_l0, pWPT0, DIN);
    permute_wT_h<<<(2048 * 2 * HDIM + 255) / 256, 256>>>(w_l1, pWPT1, 2 * HDIM);
    conv_h<<<(HDIM * 2 * HDIM + 255) / 256, 256>>>(fc1_w, pFC1h, HDIM * 2 * HDIM);

    // GEMM1: U0 = x @ WPT0^T  [32768 x 2048 x 256], fp16 out
    {
        dim3 grid(2048 / 128, M / 128);
        h_gemm<true, true, false><<<grid, 256, GSMEM>>>(pXh, pWPT0, pUh, M, 2048, DIN, nullptr);
    }
    sru_scan_kernel<<<2 * BDIM * (HDIM / 64), 64>>>((const uint2*)pUh, wc_l0, b_l0, pH0h);

    // GEMM2: U1 = H0 @ WPT1^T  [32768 x 2048 x 512], fp16 out
    {
        dim3 grid(2048 / 128, M / 128);
        h_gemm<false, true, false><<<grid, 256, GSMEM>>>(pH0h, pWPT1, pUh, M, 2048, 2 * HDIM, nullptr);
    }
    sru_scan_kernel<<<2 * BDIM * (HDIM / 64), 64>>>((const uint2*)pUh, wc_l1, b_l1, pH1h);

    // GEMM3: Y = H1 @ fc1_w^T + fc1_b  [32768 x 256 x 512], fp32 out
    {
        dim3 grid(HDIM / 128, M / 128);
        h_gemm<false, false, true><<<grid, 256, GSMEM>>>(pH1h, pFC1h, pY, M, HDIM, 2 * HDIM, fc1_b);
    }

    // logits + log_softmax
    logits_kernel<<<M / 32, 256>>>(pY, lp_w, lp_b, out);
}

// round 8
// speedup vs baseline: 2.0181x; 1.2061x over previous
#include <cuda_runtime.h>
#include <cuda_fp16.h>
#include <cstdint>
#include <cstddef>

// Problem dims (fixed by reference)
#define TDIM 1024
#define BDIM 32
#define DIN  256
#define HDIM 256
#define AADIM 21

// Scratch (device globals: allocation-guard safe)
// U layout PERMUTED, fp16: (T, B, dir, H, 4) — uint2 (4 halves) per (t,b,dir,h)
__device__ __half g_Uh  [ (size_t)TDIM * BDIM * 8 * HDIM ];   // 128 MB fp16
__device__ __half g_H0h [ (size_t)TDIM * BDIM * 2 * HDIM ];   // 32 MB fp16 (T,B,2H)
__device__ __half g_H1h [ (size_t)TDIM * BDIM * 2 * HDIM ];   // 32 MB
__device__ float  g_Y   [ (size_t)TDIM * BDIM * HDIM ];       // 32 MB (T*B, H)
__device__ __half g_Xh  [ (size_t)BDIM * TDIM * DIN ];        // x fp16 (B,T,DIN)
__device__ __half g_WPT0[ 2048 * DIN ];                       // w_l0 perm+T fp16 [2048][256]
__device__ __half g_WPT1[ 2048 * 2 * HDIM ];                  // w_l1 perm+T fp16 [2048][512]
__device__ __half g_FC1h[ HDIM * 2 * HDIM ];                  // fc1_w fp16 [256][512]

__device__ __forceinline__ void cp16(uint32_t dst, const void* src) {
    asm volatile("cp.async.cg.shared.global [%0], [%1], 16;" :: "r"(dst), "l"(src));
}
__device__ __forceinline__ uint32_t su32(const void* p) {
    return (uint32_t)__cvta_generic_to_shared(p);
}
__device__ __forceinline__ float fast_tanh(float x) {
    float r;
    asm("tanh.approx.f32 %0, %1;" : "=f"(r) : "f"(x));
    return r;
}

#define LDSM_X4(r, addr)                                                      \
    asm volatile("ldmatrix.sync.aligned.m8n8.x4.shared.b16 {%0,%1,%2,%3}, [%4];" \
                 : "=r"((r)[0]), "=r"((r)[1]), "=r"((r)[2]), "=r"((r)[3])     \
                 : "r"(addr))
#define LDSM_X2(r, addr)                                                      \
    asm volatile("ldmatrix.sync.aligned.m8n8.x2.shared.b16 {%0,%1}, [%2];"    \
                 : "=r"((r)[0]), "=r"((r)[1])                                 \
                 : "r"(addr))

// ===========================================================================
// fp16 tensor-core GEMM: C[M,N] = A[M,K](fp16) @ B^T (B fp16 [N][K])
// Block 128x128, 256 threads = 8 warps (2x4), warp tile 64x32.
// mma.m16n8k16, BK=32 halves, 3-stage cp.async pipeline, ldmatrix fragments.
// OUTH: C fp16, smem-staged coalesced stores. XMODE: A row m -> x[b][t].
// ===========================================================================
#define BKH   32                       // halves per K tile
#define LDKH  40                       // padded halves per smem row (80 B)
#define TILEB (128 * LDKH * 2)         // 10240 bytes per operand tile
#define STGB  (2 * TILEB)              // 20480 bytes per stage
#define GSMEM (3 * STGB)               // 61440 bytes
#define EPILD 136                      // epilogue stage row stride (halves)

template<bool XMODE, bool OUTH, bool BIAS>
__global__ __launch_bounds__(256)
void h_gemm(const __half* __restrict__ A, const __half* __restrict__ Bw,
            void* __restrict__ Cv, int M, int N, int K,
            const float* __restrict__ bias)
{
    extern __shared__ char smem[];
    const uint32_t smem_u = su32(smem);

    const int tid  = threadIdx.x;
    const int lane = tid & 31;
    const int wid  = tid >> 5;
    const int bm = blockIdx.y * 128;
    const int bn = blockIdx.x * 128;
    const int wm = (wid & 1) * 64;
    const int wn = (wid >> 1) * 32;
    const int g2 = lane >> 2;      // 0..7
    const int g4 = lane & 3;       // 0..3

    float acc[4][4][4];
    #pragma unroll
    for (int mi = 0; mi < 4; mi++)
        #pragma unroll
        for (int ni = 0; ni < 4; ni++)
            #pragma unroll
            for (int r = 0; r < 4; r++)
                acc[mi][ni][r] = 0.f;

    // ldmatrix per-lane row offsets (bytes within a stage tile)
    uint32_t aoff[4], boff[4];
    {
        const int al8  = lane & 7;
        const int am8  = (lane >> 3) & 1;
        const int ak16 = (lane >> 4) & 1;
        #pragma unroll
        for (int mt = 0; mt < 4; mt++)
            aoff[mt] = (uint32_t)(wm + mt * 16 + am8 * 8 + al8) * (LDKH * 2)
                     + ak16 * 16;
        const int bl8  = lane & 7;
        const int bk16 = (lane >> 3) & 1;   // lanes 16-31 mirror 0-15 (ignored)
        #pragma unroll
        for (int nt = 0; nt < 4; nt++)
            boff[nt] = (uint32_t)(wn + nt * 8 + bl8) * (LDKH * 2)
                     + bk16 * 16;
    }

    const int T_t = K / BKH;

    #define ISSUE(tile, buf)                                                  \
    {                                                                         \
        const int k0_ = (tile) * BKH;                                         \
        const uint32_t as_ = smem_u + (buf) * STGB;                           \
        const uint32_t bs_ = as_ + TILEB;                                     \
        _Pragma("unroll")                                                     \
        for (int p = 0; p < 2; p++) {                                         \
            int id  = tid + p * 256;                                          \
            int row = id >> 2;                                                \
            int c   = id & 3;                                                 \
            size_t aoffg;                                                     \
            int gm = bm + row;                                                \
            if (XMODE) {                                                      \
                int t_ = gm >> 5, bb = gm & 31;                               \
                aoffg = ((size_t)bb * TDIM + t_) * (size_t)K + k0_ + c * 8;   \
            } else {                                                          \
                aoffg = (size_t)gm * K + k0_ + c * 8;                         \
            }                                                                 \
            cp16(as_ + row * (LDKH * 2) + c * 16, A + aoffg);                 \
            cp16(bs_ + row * (LDKH * 2) + c * 16,                             \
                 Bw + (size_t)(bn + row) * K + k0_ + c * 8);                  \
        }                                                                     \
        asm volatile("cp.async.commit_group;");                               \
    }

    ISSUE(0, 0);
    ISSUE(1, 1);

    for (int t = 0; t < T_t; t++) {
        if (t + 1 < T_t) asm volatile("cp.async.wait_group 1;");
        else             asm volatile("cp.async.wait_group 0;");
        __syncthreads();

        if (t + 2 < T_t) ISSUE(t + 2, (t + 2) % 3);

        const uint32_t sa = smem_u + (t % 3) * STGB;
        const uint32_t sb = sa + TILEB;

        #pragma unroll
        for (int kk = 0; kk < 2; kk++) {
            const uint32_t kadd = kk * 32;       // 16 halves = 32 bytes
            uint32_t af[4][4], bf[4][2];
            #pragma unroll
            for (int mt = 0; mt < 4; mt++)
                LDSM_X4(af[mt], sa + aoff[mt] + kadd);
            #pragma unroll
            for (int nt = 0; nt < 4; nt++)
                LDSM_X2(bf[nt], sb + boff[nt] + kadd);
            #pragma unroll
            for (int mt = 0; mt < 4; mt++)
                #pragma unroll
                for (int nt = 0; nt < 4; nt++) {
                    asm volatile(
                        "mma.sync.aligned.m16n8k16.row.col.f32.f16.f16.f32 "
                        "{%0,%1,%2,%3}, {%4,%5,%6,%7}, {%8,%9}, {%0,%1,%2,%3};"
                        : "+f"(acc[mt][nt][0]), "+f"(acc[mt][nt][1]),
                          "+f"(acc[mt][nt][2]), "+f"(acc[mt][nt][3])
                        : "r"(af[mt][0]), "r"(af[mt][1]),
                          "r"(af[mt][2]), "r"(af[mt][3]),
                          "r"(bf[nt][0]), "r"(bf[nt][1]));
                }
        }
    }
    #undef ISSUE

    if (OUTH) {
        // fp16 output: stage 32x128 chunks in smem, store coalesced
        __half* Ch = (__half*)Cv;
        __half* st = (__half*)smem;
        #pragma unroll
        for (int mt = 0; mt < 4; mt++) {
            __syncthreads();
            const int srow = (wid & 1) * 16 + g2;
            #pragma unroll
            for (int nt = 0; nt < 4; nt++) {
                const int scol = wn + nt * 8 + 2 * g4;
                __half2 v01 = __floats2half2_rn(acc[mt][nt][0], acc[mt][nt][1]);
                __half2 v23 = __floats2half2_rn(acc[mt][nt][2], acc[mt][nt][3]);
                *(__half2*)&st[srow * EPILD + scol]       = v01;
                *(__half2*)&st[(srow + 8) * EPILD + scol] = v23;
            }
            __syncthreads();
            const int s   = tid >> 3;              // 0..31
            const int c16 = (tid & 7) * 16;        // 0..112
            const int crow = bm + (s >> 4) * 64 + mt * 16 + (s & 15);
            uint4 v0 = *(uint4*)&st[s * EPILD + c16];
            uint4 v1 = *(uint4*)&st[s * EPILD + c16 + 8];
            *(uint4*)(Ch + (size_t)crow * N + bn + c16)     = v0;
            *(uint4*)(Ch + (size_t)crow * N + bn + c16 + 8) = v1;
        }
    } else {
        float* C = (float*)Cv;
        #pragma unroll
        for (int mt = 0; mt < 4; mt++) {
            int row0 = bm + wm + mt * 16 + g2;
            #pragma unroll
            for (int nt = 0; nt < 4; nt++) {
                int col = bn + wn + nt * 8 + 2 * g4;
                float bx = 0.f, by = 0.f;
                if (BIAS) { bx = bias[col]; by = bias[col + 1]; }
                float2 v0 = make_float2(acc[mt][nt][0] + bx, acc[mt][nt][1] + by);
                float2 v1 = make_float2(acc[mt][nt][2] + bx, acc[mt][nt][3] + by);
                *(float2*)(C + (size_t)row0 * N + col)       = v0;
                *(float2*)(C + (size_t)(row0 + 8) * N + col) = v1;
            }
        }
    }
}

// ---------------------------------------------------------------------------
// Prep: fp32 -> fp16 conversions
// ---------------------------------------------------------------------------
__global__ void conv_h(const float* __restrict__ in, __half* __restrict__ out,
                       int n)
{
    int i = blockIdx.x * blockDim.x + threadIdx.x;
    if (i < n) out[i] = __float2half(in[i]);
}

// Permute + transpose weights to fp16: wpt[p][k] = w[k][n(p)].
__global__ void permute_wT_h(const float* __restrict__ w, __half* __restrict__ wpt,
                             int K)
{
    int idx = blockIdx.x * blockDim.x + threadIdx.x;   // p-major, k fastest
    if (idx >= 2048 * K) return;
    int p = idx / K;
    int k = idx % K;
    int dir = p >> 10;
    int h   = (p & 1023) >> 2;
    int kk  = p & 3;
    int n   = dir * 1024 + kk * 256 + h;
    wpt[idx] = __float2half(w[(size_t)k * 2048 + n]);
}

// ---------------------------------------------------------------------------
// SRU scan, fp16 U layout (T,B,dir,H,4) as uint2, depth-16 ring buffer.
// sigmoid(z) = 0.5*(1+tanh(z/2)); critical chain FFMA -> TANH -> FFMA (~24cyc).
// ---------------------------------------------------------------------------
#define SCAN_D 16

__global__ __launch_bounds__(64)
void sru_scan_kernel(const uint2* __restrict__ U2, const float* __restrict__ wc,
                     const float* __restrict__ bvec, __half* __restrict__ Hout)
{
    const int q   = HDIM / 64;                       // 4
    const int bi  = blockIdx.x;
    const int dir = bi / (BDIM * q);
    const int b   = (bi / q) % BDIM;
    const int h   = (bi % q) * 64 + threadIdx.x;

    // halved gate params (tanh form)
    const float hvf = 0.5f * wc[(dir * 2 + 0) * HDIM + h];
    const float hvr = 0.5f * wc[(dir * 2 + 1) * HDIM + h];
    const float hbf = 0.5f * bvec[(dir * 2 + 0) * HDIM + h];
    const float hbr = 0.5f * bvec[(dir * 2 + 1) * HDIM + h];

    const int t0 = dir ? (TDIM - 1) : 0;
    const long dt = dir ? -1 : 1;

    const uint2* up = U2 + (((size_t)t0 * BDIM + b) * 2 + dir) * HDIM + h;
    __half* hp = Hout + ((size_t)t0 * BDIM + b) * (2 * HDIM)
                      + (size_t)dir * HDIM + h;
    const long ustep = dt * (long)BDIM * 2 * HDIM;    // uint2 units
    const long hstep = dt * (long)BDIM * 2 * HDIM;    // half units

    uint2 ring[SCAN_D];
    const uint2* lp = up;
    #pragma unroll
    for (int d = 0; d < SCAN_D; d++) { ring[d] = *lp; lp += ustep; }

    float c = 0.f;
    for (int s0 = 0; s0 < TDIM; s0 += SCAN_D) {
        #pragma unroll
        for (int d = 0; d < SCAN_D; d++) {
            uint2 uw = ring[d];
            if (s0 + d + SCAN_D < TDIM) { ring[d] = *lp; lp += ustep; }
            float2 u01 = __half22float2(*(__half2*)&uw.x);   // (cand, forget)
            float2 u23 = __half22float2(*(__half2*)&uw.y);   // (reset, highway)
            // off-chain precompute
            float zf = fmaf(u01.y, 0.5f, hbf);
            float zr = fmaf(u23.x, 0.5f, hbr);
            float cp_ = 0.5f * (c + u01.x);
            float cm_ = 0.5f * (c - u01.x);
            // chain: FFMA -> TANH -> FFMA
            float thf = fast_tanh(fmaf(hvf, c, zf));
            float c2  = fmaf(thf, cm_, cp_);
            // r-gate off the next-step chain (uses old c)
            float thr = fast_tanh(fmaf(hvr, c, zr));
            float hv  = fmaf(thr, 0.5f * (c2 - u23.y), 0.5f * (c2 + u23.y));
            c = c2;
            *hp = __float2half(hv);
            hp += hstep;
        }
    }
}

// ---------------------------------------------------------------------------
// logits = log_softmax(Y @ lp_w^T + lp_b). 4 rows per warp, 32 rows/block.
// ---------------------------------------------------------------------------
__global__ __launch_bounds__(256)
void logits_kernel(const float* __restrict__ Y, const float* __restrict__ lp_w,
                   const float* __restrict__ lp_b, float* __restrict__ out)
{
    __shared__ float ws[AADIM * HDIM];
    __shared__ float bs[32];
    const int tid = threadIdx.x;
    for (int i = tid; i < AADIM * HDIM; i += blockDim.x) ws[i] = lp_w[i];
    if (tid < AADIM) bs[tid] = lp_b[tid];
    __syncthreads();

    const int warp = tid >> 5;
    const int lane = tid & 31;

    #pragma unroll
    for (int rr = 0; rr < 4; rr++) {
        const int row = blockIdx.x * 32 + warp * 4 + rr;   // row = t*B + b
        const int t = row / BDIM;
        const int b = row % BDIM;

        const float* y = Y + (size_t)row * HDIM;
        float yv[8];
        #pragma unroll
        for (int i = 0; i < 8; i++) yv[i] = y[lane + 32 * i];

        float lg[AADIM];
        #pragma unroll
        for (int a = 0; a < AADIM; a++) {
            float s = 0.f;
            #pragma unroll
            for (int i = 0; i < 8; i++) s += yv[i] * ws[a * HDIM + lane + 32 * i];
            #pragma unroll
            for (int off = 16; off > 0; off >>= 1)
                s += __shfl_xor_sync(0xFFFFFFFFu, s, off);
            lg[a] = s + bs[a];
        }

        float mx = lg[0];
        #pragma unroll
        for (int a = 1; a < AADIM; a++) mx = fmaxf(mx, lg[a]);
        float se = 0.f;
        #pragma unroll
        for (int a = 0; a < AADIM; a++) se += __expf(lg[a] - mx);
        float lse = mx + __logf(se);

        float myv = 0.f;
        #pragma unroll
        for (int a = 0; a < AADIM; a++) if (lane == a) myv = lg[a] - lse;
        if (lane < AADIM)
            out[((size_t)b * TDIM + t) * AADIM + lane] = myv;
    }
}

// ---------------------------------------------------------------------------
extern "C" void kernel_launch(void* const* d_in, const int* in_sizes, int n_in,
                              void* d_out, int out_size)
{
    const float* x     = (const float*)d_in[0];
    // d_in[1] = hidden (unused)
    const float* w_l0  = (const float*)d_in[2];
    const float* wc_l0 = (const float*)d_in[3];
    const float* b_l0  = (const float*)d_in[4];
    const float* w_l1  = (const float*)d_in[5];
    const float* wc_l1 = (const float*)d_in[6];
    const float* b_l1  = (const float*)d_in[7];
    const float* fc1_w = (const float*)d_in[8];
    const float* fc1_b = (const float*)d_in[9];
    const float* lp_w  = (const float*)d_in[10];
    const float* lp_b  = (const float*)d_in[11];
    float* out = (float*)d_out;

    float *pY;
    __half *pUh, *pH0h, *pH1h, *pXh, *pWPT0, *pWPT1, *pFC1h;
    cudaGetSymbolAddress((void**)&pUh,   g_Uh);
    cudaGetSymbolAddress((void**)&pY,    g_Y);
    cudaGetSymbolAddress((void**)&pH0h,  g_H0h);
    cudaGetSymbolAddress((void**)&pH1h,  g_H1h);
    cudaGetSymbolAddress((void**)&pXh,   g_Xh);
    cudaGetSymbolAddress((void**)&pWPT0, g_WPT0);
    cudaGetSymbolAddress((void**)&pWPT1, g_WPT1);
    cudaGetSymbolAddress((void**)&pFC1h, g_FC1h);

    cudaFuncSetAttribute(h_gemm<true,  true,  false>,
        cudaFuncAttributeMaxDynamicSharedMemorySize, GSMEM);
    cudaFuncSetAttribute(h_gemm<false, true,  false>,
        cudaFuncAttributeMaxDynamicSharedMemorySize, GSMEM);
    cudaFuncSetAttribute(h_gemm<false, false, true>,
        cudaFuncAttributeMaxDynamicSharedMemorySize, GSMEM);

    const int M = TDIM * BDIM;      // 32768

    // prep conversions
    conv_h<<<(BDIM * TDIM * DIN + 255) / 256, 256>>>(x, pXh, BDIM * TDIM * DIN);
    permute_wT_h<<<(2048 * DIN + 255) / 256, 256>>>(w_l0, pWPT0, DIN);
    permute_wT_h<<<(2048 * 2 * HDIM + 255) / 256, 256>>>(w_l1, pWPT1, 2 * HDIM);
    conv_h<<<(HDIM * 2 * HDIM + 255) / 256, 256>>>(fc1_w, pFC1h, HDIM * 2 * HDIM);

    // GEMM1: U0 = x @ WPT0^T  [32768 x 2048 x 256], fp16 out
    {
        dim3 grid(2048 / 128, M / 128);
        h_gemm<true, true, false><<<grid, 256, GSMEM>>>(pXh, pWPT0, pUh, M, 2048, DIN, nullptr);
    }
    sru_scan_kernel<<<2 * BDIM * (HDIM / 64), 64>>>((const uint2*)pUh, wc_l0, b_l0, pH0h);

    // GEMM2: U1 = H0 @ WPT1^T  [32768 x 2048 x 512], fp16 out
    {
        dim3 grid(2048 / 128, M / 128);
        h_gemm<false, true, false><<<grid, 256, GSMEM>>>(pH0h, pWPT1, pUh, M, 2048, 2 * HDIM, nullptr);
    }
    sru_scan_kernel<<<2 * BDIM * (HDIM / 64), 64>>>((const uint2*)pUh, wc_l1, b_l1, pH1h);

    // GEMM3: Y = H1 @ fc1_w^T + fc1_b  [32768 x 256 x 512], fp32 out
    {
        dim3 grid(HDIM / 128, M / 128);
        h_gemm<false, false, true><<<grid, 256, GSMEM>>>(pH1h, pFC1h, pY, M, HDIM, 2 * HDIM, fc1_b);
    }

    // logits + log_softmax
    logits_kernel<<<M / 32, 256>>>(pY, lp_w, lp_b, out);
}

// round 13
// speedup vs baseline: 2.0848x; 1.0331x over previous
#include <cuda_runtime.h>
#include <cuda_fp16.h>
#include <cstdint>
#include <cstddef>

// Problem dims (fixed by reference)
#define TDIM 1024
#define BDIM 32
#define DIN  256
#define HDIM 256
#define AADIM 21

// Scratch (device globals: allocation-guard safe)
// U layout PERMUTED, fp16: (T, B, dir, H, 4) — uint2 (4 halves) per (t,b,dir,h)
__device__ __half g_Uh  [ (size_t)TDIM * BDIM * 8 * HDIM ];   // 128 MB fp16
__device__ __half g_H0h [ (size_t)TDIM * BDIM * 2 * HDIM ];   // 32 MB fp16 (T,B,2H)
__device__ __half g_H1h [ (size_t)TDIM * BDIM * 2 * HDIM ];   // 32 MB
__device__ __half g_Xh  [ (size_t)BDIM * TDIM * DIN ];        // x fp16 (B,T,DIN)
__device__ __half g_WPT0[ 2048 * DIN ];                       // w_l0 perm+T fp16 [2048][256]
__device__ __half g_WPT1[ 2048 * 2 * HDIM ];                  // w_l1 perm+T fp16 [2048][512]
__device__ __half g_FC1h[ HDIM * 2 * HDIM ];                  // fc1_w fp16 [256][512]

__device__ __forceinline__ void cp16(uint32_t dst, const void* src) {
    asm volatile("cp.async.cg.shared.global [%0], [%1], 16;" :: "r"(dst), "l"(src));
}
__device__ __forceinline__ uint32_t su32(const void* p) {
    return (uint32_t)__cvta_generic_to_shared(p);
}
__device__ __forceinline__ float fast_tanh(float x) {
    float r;
    asm("tanh.approx.f32 %0, %1;" : "=f"(r) : "f"(x));
    return r;
}

#define LDSM_X4(r, addr)                                                      \
    asm volatile("ldmatrix.sync.aligned.m8n8.x4.shared.b16 {%0,%1,%2,%3}, [%4];" \
                 : "=r"((r)[0]), "=r"((r)[1]), "=r"((r)[2]), "=r"((r)[3])     \
                 : "r"(addr))
#define LDSM_X2(r, addr)                                                      \
    asm volatile("ldmatrix.sync.aligned.m8n8.x2.shared.b16 {%0,%1}, [%2];"    \
                 : "=r"((r)[0]), "=r"((r)[1])                                 \
                 : "r"(addr))

#define MMA16816(d, a, b0, b1)                                                \
    asm volatile("mma.sync.aligned.m16n8k16.row.col.f32.f16.f16.f32 "         \
                 "{%0,%1,%2,%3}, {%4,%5,%6,%7}, {%8,%9}, {%0,%1,%2,%3};"      \
                 : "+f"((d)[0]), "+f"((d)[1]), "+f"((d)[2]), "+f"((d)[3])     \
                 : "r"((a)[0]), "r"((a)[1]), "r"((a)[2]), "r"((a)[3]),        \
                   "r"(b0), "r"(b1))

// ===========================================================================
// ROUND-8 PROVEN GEMM (verbatim): block 128x128, 256 threads = 8 warps (2x4),
// warp tile 64x32, mma.m16n8k16, BK=32 halves, 3-stage cp.async, ldmatrix.
// fp16 C via smem-staged coalesced stores. XMODE: A row m -> x[b][t].
// ===========================================================================
#define BKH   32                       // halves per K tile
#define LDKH  40                       // padded halves per smem row (80 B)
#define ROWB  (LDKH * 2)               // 80 bytes
#define TILEB (128 * ROWB)             // 10240 bytes per operand tile
#define STGB  (2 * TILEB)              // 20480 bytes per stage
#define GSMEM (3 * STGB)               // 61440 bytes
#define EPILD 136                      // epilogue stage row stride (halves)

template<bool XMODE>
__global__ __launch_bounds__(256)
void h_gemm(const __half* __restrict__ A, const __half* __restrict__ Bw,
            __half* __restrict__ Ch, int M, int N, int K)
{
    extern __shared__ char smem[];
    const uint32_t smem_u = su32(smem);

    const int tid  = threadIdx.x;
    const int lane = tid & 31;
    const int wid  = tid >> 5;
    const int bm = blockIdx.y * 128;
    const int bn = blockIdx.x * 128;
    const int wm = (wid & 1) * 64;
    const int wn = (wid >> 1) * 32;
    const int g2 = lane >> 2;      // 0..7
    const int g4 = lane & 3;       // 0..3

    float acc[4][4][4];
    #pragma unroll
    for (int mi = 0; mi < 4; mi++)
        #pragma unroll
        for (int ni = 0; ni < 4; ni++)
            #pragma unroll
            for (int r = 0; r < 4; r++)
                acc[mi][ni][r] = 0.f;

    // ldmatrix per-lane offsets (bytes within a stage tile)
    uint32_t aoff[4], boff[4];
    {
        const int al8  = lane & 7;
        const int am8  = (lane >> 3) & 1;
        const int ak16 = (lane >> 4) & 1;
        #pragma unroll
        for (int mt = 0; mt < 4; mt++)
            aoff[mt] = (uint32_t)(wm + mt * 16 + am8 * 8 + al8) * ROWB
                     + ak16 * 16;
        const int bl8  = lane & 7;
        const int bk16 = (lane >> 3) & 1;   // lanes 16-31 mirror 0-15 (ignored)
        #pragma unroll
        for (int nt = 0; nt < 4; nt++)
            boff[nt] = (uint32_t)(wn + nt * 8 + bl8) * ROWB
                     + bk16 * 16;
    }

    const int T_t = K / BKH;

    #define ISSUE(tile, buf)                                                  \
    {                                                                         \
        const int k0_ = (tile) * BKH;                                         \
        const uint32_t as_ = smem_u + (buf) * STGB;                           \
        const uint32_t bs_ = as_ + TILEB;                                     \
        _Pragma("unroll")                                                     \
        for (int p = 0; p < 2; p++) {                                         \
            int id  = tid + p * 256;                                          \
            int row = id >> 2;                                                \
            int c   = id & 3;                                                 \
            size_t aoffg;                                                     \
            int gm = bm + row;                                                \
            if (XMODE) {                                                      \
                int t_ = gm >> 5, bb = gm & 31;                               \
                aoffg = ((size_t)bb * TDIM + t_) * (size_t)K + k0_ + c * 8;   \
            } else {                                                          \
                aoffg = (size_t)gm * K + k0_ + c * 8;                         \
            }                                                                 \
            cp16(as_ + row * ROWB + c * 16, A + aoffg);                       \
            cp16(bs_ + row * ROWB + c * 16,                                   \
                 Bw + (size_t)(bn + row) * K + k0_ + c * 8);                  \
        }                                                                     \
        asm volatile("cp.async.commit_group;");                               \
    }

    ISSUE(0, 0);
    ISSUE(1, 1);

    for (int t = 0; t < T_t; t++) {
        if (t + 1 < T_t) asm volatile("cp.async.wait_group 1;");
        else             asm volatile("cp.async.wait_group 0;");
        __syncthreads();

        if (t + 2 < T_t) ISSUE(t + 2, (t + 2) % 3);

        const uint32_t sa = smem_u + (t % 3) * STGB;
        const uint32_t sb = sa + TILEB;

        #pragma unroll
        for (int kk = 0; kk < 2; kk++) {
            const uint32_t kadd = kk * 32;       // 16 halves = 32 bytes
            uint32_t af[4][4], bf[4][2];
            #pragma unroll
            for (int mt = 0; mt < 4; mt++)
                LDSM_X4(af[mt], sa + aoff[mt] + kadd);
            #pragma unroll
            for (int nt = 0; nt < 4; nt++)
                LDSM_X2(bf[nt], sb + boff[nt] + kadd);
            #pragma unroll
            for (int mt = 0; mt < 4; mt++)
                #pragma unroll
                for (int nt = 0; nt < 4; nt++)
                    MMA16816(acc[mt][nt], af[mt], bf[nt][0], bf[nt][1]);
        }
    }
    #undef ISSUE

    // fp16 output: stage 32x128 chunks in smem, store coalesced
    {
        __half* st = (__half*)smem;
        #pragma unroll
        for (int mt = 0; mt < 4; mt++) {
            __syncthreads();
            const int srow = (wid & 1) * 16 + g2;
            #pragma unroll
            for (int ni = 0; ni < 4; ni++) {
                const int scol = wn + ni * 8 + 2 * g4;
                __half2 v01 = __floats2half2_rn(acc[mt][ni][0], acc[mt][ni][1]);
                __half2 v23 = __floats2half2_rn(acc[mt][ni][2], acc[mt][ni][3]);
                *(__half2*)&st[srow * EPILD + scol]       = v01;
                *(__half2*)&st[(srow + 8) * EPILD + scol] = v23;
            }
            __syncthreads();
            const int s   = tid >> 3;              // 0..31
            const int c16 = (tid & 7) * 16;        // 0..112
            const int crow = bm + (s >> 4) * 64 + mt * 16 + (s & 15);
            #pragma unroll
            for (int q = 0; q < 2; q++) {
                uint4 v = *(uint4*)&st[s * EPILD + c16 + q * 8];
                *(uint4*)(Ch + (size_t)crow * N + bn + c16 + q * 8) = v;
            }
        }
    }
}

// ===========================================================================
// Fused GEMM3 + fc1 bias + logits + log_softmax.
// BM=64, BN=256 (full N), 256 threads = 8 warps (1x8), warp tile 64x32 —
// warp-tile internals identical to the proven round-8 mainloop (wm = 0).
// A = H1 [M][512] fp16, B = fc1_w fp16 [256][512]. K=512 fixed.
// ===========================================================================
#define F3_ATILB (64 * ROWB)                 // 5120 B
#define F3_BTILB (256 * ROWB)                // 20480 B
#define F3_STGB  (F3_ATILB + F3_BTILB)       // 25600 B
#define F3_WS    (3 * F3_STGB)               // 76800: lp_w fp32
#define F3_BS    (F3_WS + AADIM * HDIM * 4)  // + 21504
#define F3_SMEM  (F3_BS + 1024)              // 99328 B
#define F3_EPF   268                         // fp32 staging stride (floats)

__global__ __launch_bounds__(256)
void fused_gemm3(const __half* __restrict__ A, const __half* __restrict__ Bw,
                 const float* __restrict__ fc1_b, const float* __restrict__ lp_w,
                 const float* __restrict__ lp_b, float* __restrict__ out)
{
    extern __shared__ char smem[];
    const uint32_t smem_u = su32(smem);
    const int K = 2 * HDIM;                  // 512

    const int tid  = threadIdx.x;
    const int lane = tid & 31;
    const int wid  = tid >> 5;
    const int bm = blockIdx.x * 64;
    const int wn = wid * 32;
    const int g2 = lane >> 2;
    const int g4 = lane & 3;

    {
        float* ws = (float*)(smem + F3_WS);
        float* bs = (float*)(smem + F3_BS);
        for (int i = tid; i < AADIM * HDIM; i += 256) ws[i] = lp_w[i];
        if (tid < HDIM) bs[tid] = fc1_b[tid];
    }

    float acc[4][4][4];
    #pragma unroll
    for (int mi = 0; mi < 4; mi++)
        #pragma unroll
        for (int ni = 0; ni < 4; ni++)
            #pragma unroll
            for (int r = 0; r < 4; r++)
                acc[mi][ni][r] = 0.f;

    uint32_t aoff[4], boff[4];
    {
        const int al8  = lane & 7;
        const int am8  = (lane >> 3) & 1;
        const int ak16 = (lane >> 4) & 1;
        #pragma unroll
        for (int mt = 0; mt < 4; mt++)
            aoff[mt] = (uint32_t)(mt * 16 + am8 * 8 + al8) * ROWB + ak16 * 16;
        const int bk16 = (lane >> 3) & 1;
        #pragma unroll
        for (int nt = 0; nt < 4; nt++)
            boff[nt] = (uint32_t)(wn + nt * 8 + al8) * ROWB + bk16 * 16;
    }

    const int T_t = K / BKH;                 // 16

    #define F3_ISSUE(tile, buf)                                               \
    {                                                                         \
        const int k0_ = (tile) * BKH;                                         \
        const uint32_t as_ = smem_u + (buf) * F3_STGB;                        \
        const uint32_t bs_ = as_ + F3_ATILB;                                  \
        {                                                                     \
            int row = tid >> 2, c = tid & 3;                                  \
            cp16(as_ + row * ROWB + c * 16,                                   \
                 A + (size_t)(bm + row) * K + k0_ + c * 8);                   \
        }                                                                     \
        _Pragma("unroll")                                                     \
        for (int p = 0; p < 4; p++) {                                         \
            int id = tid + p * 256;                                           \
            int row = id >> 2, c = id & 3;                                    \
            cp16(bs_ + row * ROWB + c * 16,                                   \
                 Bw + (size_t)row * K + k0_ + c * 8);                         \
        }                                                                     \
        asm volatile("cp.async.commit_group;");                               \
    }

    F3_ISSUE(0, 0);
    F3_ISSUE(1, 1);

    for (int t = 0; t < T_t; t++) {
        if (t + 1 < T_t) asm volatile("cp.async.wait_group 1;");
        else             asm volatile("cp.async.wait_group 0;");
        __syncthreads();

        if (t + 2 < T_t) F3_ISSUE(t + 2, (t + 2) % 3);

        const uint32_t sa = smem_u + (t % 3) * F3_STGB;
        const uint32_t sb = sa + F3_ATILB;

        #pragma unroll
        for (int kk = 0; kk < 2; kk++) {
            const uint32_t kadd = kk * 32;
            uint32_t af[4][4], bf[4][2];
            #pragma unroll
            for (int mt = 0; mt < 4; mt++)
                LDSM_X4(af[mt], sa + aoff[mt] + kadd);
            #pragma unroll
            for (int nt = 0; nt < 4; nt++)
                LDSM_X2(bf[nt], sb + boff[nt] + kadd);
            #pragma unroll
            for (int mt = 0; mt < 4; mt++)
                #pragma unroll
                for (int nt = 0; nt < 4; nt++)
                    MMA16816(acc[mt][nt], af[mt], bf[nt][0], bf[nt][1]);
        }
    }
    #undef F3_ISSUE

    // fused epilogue: per 16-row chunk, stage fp32 Y (+bias), logits, softmax
    float* st = (float*)smem;
    const float* ws = (const float*)(smem + F3_WS);
    const float* bs = (const float*)(smem + F3_BS);
    #pragma unroll
    for (int mt = 0; mt < 4; mt++) {
        __syncthreads();
        #pragma unroll
        for (int nt = 0; nt < 4; nt++) {
            const int scol = wn + nt * 8 + 2 * g4;
            float b0 = bs[scol], b1 = bs[scol + 1];
            *(float2*)&st[g2 * F3_EPF + scol] =
                make_float2(acc[mt][nt][0] + b0, acc[mt][nt][1] + b1);
            *(float2*)&st[(g2 + 8) * F3_EPF + scol] =
                make_float2(acc[mt][nt][2] + b0, acc[mt][nt][3] + b1);
        }
        __syncthreads();
        #pragma unroll
        for (int rr = 0; rr < 2; rr++) {
            const int s = wid * 2 + rr;              // 0..15
            const int row = bm + mt * 16 + s;        // m = t*32 + b
            const int tt = row >> 5;
            const int bb = row & 31;
            float yv[8];
            #pragma unroll
            for (int i = 0; i < 8; i++) yv[i] = st[s * F3_EPF + lane + 32 * i];
            float lg[AADIM];
            #pragma unroll
            for (int a = 0; a < AADIM; a++) {
                float sum = 0.f;
                #pragma unroll
                for (int i = 0; i < 8; i++)
                    sum += yv[i] * ws[a * HDIM + lane + 32 * i];
                #pragma unroll
                for (int off = 16; off > 0; off >>= 1)
                    sum += __shfl_xor_sync(0xFFFFFFFFu, sum, off);
                lg[a] = sum + lp_b[a];
            }
            float mx = lg[0];
            #pragma unroll
            for (int a = 1; a < AADIM; a++) mx = fmaxf(mx, lg[a]);
            float se = 0.f;
            #pragma unroll
            for (int a = 0; a < AADIM; a++) se += __expf(lg[a] - mx);
            float lse = mx + __logf(se);
            float myv = 0.f;
            #pragma unroll
            for (int a = 0; a < AADIM; a++) if (lane == a) myv = lg[a] - lse;
            if (lane < AADIM)
                out[((size_t)bb * TDIM + tt) * AADIM + lane] = myv;
        }
    }
}

// ---------------------------------------------------------------------------
// Prep: fp32 -> fp16 conversions
// ---------------------------------------------------------------------------
__global__ void conv_h(const float* __restrict__ in, __half* __restrict__ out,
                       int n)
{
    int i = blockIdx.x * blockDim.x + threadIdx.x;
    if (i < n) out[i] = __float2half(in[i]);
}

// Permute + transpose weights to fp16: wpt[p][k] = w[k][n(p)].
__global__ void permute_wT_h(const float* __restrict__ w, __half* __restrict__ wpt,
                             int K)
{
    int idx = blockIdx.x * blockDim.x + threadIdx.x;   // p-major, k fastest
    if (idx >= 2048 * K) return;
    int p = idx / K;
    int k = idx % K;
    int dir = p >> 10;
    int h   = (p & 1023) >> 2;
    int kk  = p & 3;
    int n   = dir * 1024 + kk * 256 + h;
    wpt[idx] = __float2half(w[(size_t)k * 2048 + n]);
}

// ---------------------------------------------------------------------------
// SRU scan, fp16 U layout (T,B,dir,H,4) as uint2, depth-32 ring buffer.
// sigmoid(z) = 0.5*(1+tanh(z/2)); chain FFMA -> TANH -> FFMA (~24cyc).
// ---------------------------------------------------------------------------
#define SCAN_D 32

__global__ __launch_bounds__(64)
void sru_scan_kernel(const uint2* __restrict__ U2, const float* __restrict__ wc,
                     const float* __restrict__ bvec, __half* __restrict__ Hout)
{
    const int q   = HDIM / 64;                       // 4
    const int bi  = blockIdx.x;
    const int dir = bi / (BDIM * q);
    const int b   = (bi / q) % BDIM;
    const int h   = (bi % q) * 64 + threadIdx.x;

    // halved gate params (tanh form)
    const float hvf = 0.5f * wc[(dir * 2 + 0) * HDIM + h];
    const float hvr = 0.5f * wc[(dir * 2 + 1) * HDIM + h];
    const float hbf = 0.5f * bvec[(dir * 2 + 0) * HDIM + h];
    const float hbr = 0.5f * bvec[(dir * 2 + 1) * HDIM + h];

    const int t0 = dir ? (TDIM - 1) : 0;
    const long dt = dir ? -1 : 1;

    const uint2* up = U2 + (((size_t)t0 * BDIM + b) * 2 + dir) * HDIM + h;
    __half* hp = Hout + ((size_t)t0 * BDIM + b) * (2 * HDIM)
                      + (size_t)dir * HDIM + h;
    const long ustep = dt * (long)BDIM * 2 * HDIM;    // uint2 units
    const long hstep = dt * (long)BDIM * 2 * HDIM;    // half units

    uint2 ring[SCAN_D];
    const uint2* lp = up;
    #pragma unroll
    for (int d = 0; d < SCAN_D; d++) { ring[d] = *lp; lp += ustep; }

    float c = 0.f;
    for (int s0 = 0; s0 < TDIM; s0 += SCAN_D) {
        #pragma unroll
        for (int d = 0; d < SCAN_D; d++) {
            uint2 uw = ring[d];
            if (s0 + d + SCAN_D < TDIM) { ring[d] = *lp; lp += ustep; }
            float2 u01 = __half22float2(*(__half2*)&uw.x);   // (cand, forget)
            float2 u23 = __half22float2(*(__half2*)&uw.y);   // (reset, highway)
            float zf = fmaf(u01.y, 0.5f, hbf);
            float zr = fmaf(u23.x, 0.5f, hbr);
            float cp_ = 0.5f * (c + u01.x);
            float cm_ = 0.5f * (c - u01.x);
            float thf = fast_tanh(fmaf(hvf, c, zf));
            float c2  = fmaf(thf, cm_, cp_);
            float thr = fast_tanh(fmaf(hvr, c, zr));
            float hv  = fmaf(thr, 0.5f * (c2 - u23.y), 0.5f * (c2 + u23.y));
            c = c2;
            *hp = __float2half(hv);
            hp += hstep;
        }
    }
}

// ---------------------------------------------------------------------------
extern "C" void kernel_launch(void* const* d_in, const int* in_sizes, int n_in,
                              void* d_out, int out_size)
{
    const float* x     = (const float*)d_in[0];
    // d_in[1] = hidden (unused)
    const float* w_l0  = (const float*)d_in[2];
    const float* wc_l0 = (const float*)d_in[3];
    const float* b_l0  = (const float*)d_in[4];
    const float* w_l1  = (const float*)d_in[5];
    const float* wc_l1 = (const float*)d_in[6];
    const float* b_l1  = (const float*)d_in[7];
    const float* fc1_w = (const float*)d_in[8];
    const float* fc1_b = (const float*)d_in[9];
    const float* lp_w  = (const float*)d_in[10];
    const float* lp_b  = (const float*)d_in[11];
    float* out = (float*)d_out;

    __half *pUh, *pH0h, *pH1h, *pXh, *pWPT0, *pWPT1, *pFC1h;
    cudaGetSymbolAddress((void**)&pUh,   g_Uh);
    cudaGetSymbolAddress((void**)&pH0h,  g_H0h);
    cudaGetSymbolAddress((void**)&pH1h,  g_H1h);
    cudaGetSymbolAddress((void**)&pXh,   g_Xh);
    cudaGetSymbolAddress((void**)&pWPT0, g_WPT0);
    cudaGetSymbolAddress((void**)&pWPT1, g_WPT1);
    cudaGetSymbolAddress((void**)&pFC1h, g_FC1h);

    cudaFuncSetAttribute(h_gemm<true>,
        cudaFuncAttributeMaxDynamicSharedMemorySize, GSMEM);
    cudaFuncSetAttribute(h_gemm<false>,
        cudaFuncAttributeMaxDynamicSharedMemorySize, GSMEM);
    cudaFuncSetAttribute(fused_gemm3,
        cudaFuncAttributeMaxDynamicSharedMemorySize, F3_SMEM);

    const int M = TDIM * BDIM;      // 32768

    // prep conversions
    conv_h<<<(BDIM * TDIM * DIN + 255) / 256, 256>>>(x, pXh, BDIM * TDIM * DIN);
    permute_wT_h<<<(2048 * DIN + 255) / 256, 256>>>(w_l0, pWPT0, DIN);
    permute_wT_h<<<(2048 * 2 * HDIM + 255) / 256, 256>>>(w_l1, pWPT1, 2 * HDIM);
    conv_h<<<(HDIM * 2 * HDIM + 255) / 256, 256>>>(fc1_w, pFC1h, HDIM * 2 * HDIM);

    // GEMM1: U0 = x @ WPT0^T  [32768 x 2048 x 256], fp16 out
    {
        dim3 grid(2048 / 128, M / 128);
        h_gemm<true><<<grid, 256, GSMEM>>>(pXh, pWPT0, pUh, M, 2048, DIN);
    }
    sru_scan_kernel<<<2 * BDIM * (HDIM / 64), 64>>>((const uint2*)pUh, wc_l0, b_l0, pH0h);

    // GEMM2: U1 = H0 @ WPT1^T  [32768 x 2048 x 512], fp16 out
    {
        dim3 grid(2048 / 128, M / 128);
        h_gemm<false><<<grid, 256, GSMEM>>>(pH0h, pWPT1, pUh, M, 2048, 2 * HDIM);
    }
    sru_scan_kernel<<<2 * BDIM * (HDIM / 64), 64>>>((const uint2*)pUh, wc_l1, b_l1, pH1h);

    // GEMM3 + fc1_b + logits + log_softmax fused
    fused_gemm3<<<M / 64, 256, F3_SMEM>>>(pH1h, pFC1h, fc1_b, lp_w, lp_b, out);
}